// round 3
// baseline (speedup 1.0000x reference)
#include <cuda_runtime.h>
#include <math.h>

#define EMB   1024
#define SEQ   2048
#define BATCH 2
#define MTOK  (BATCH*SEQ)   // 4096 rows
#define FF    4096
#define HEADS 16
#define HD    64

// ---------------- single scratch arena (static; no cudaMalloc) -------------
// layout (floats):
//   h   : [0,            4M)          4M = MTOK*EMB
//   q   : [4M,           8M)
//   k   : [8M,          12M)
//   v   : [12M,         16M)
//   ctx : [16M,         20M)
//   x1  : [20M,         24M)
//   h2  : [24M,         28M)
//   ffn : [28M,         44M)          16M = MTOK*FF
#define SLOT ((size_t)MTOK*EMB)
__device__ float g_arena[SLOT*7 + (size_t)MTOK*FF];

// ---------------- LayerNorm: one block per row ------------------------------
__global__ __launch_bounds__(256)
void ln_kernel(const float* __restrict__ x, const float* __restrict__ scale,
               const float* __restrict__ shift, float* __restrict__ y)
{
    int row = blockIdx.x;
    int tid = threadIdx.x;
    const float4* xr = (const float4*)(x + (size_t)row*EMB);
    float4 v = xr[tid];
    float s  = v.x+v.y+v.z+v.w;
    float ss = v.x*v.x+v.y*v.y+v.z*v.z+v.w*v.w;
    #pragma unroll
    for (int o = 16; o > 0; o >>= 1) {
        s  += __shfl_xor_sync(0xffffffffu, s,  o);
        ss += __shfl_xor_sync(0xffffffffu, ss, o);
    }
    __shared__ float rs[8], rss[8];
    __shared__ float s_mean, s_rstd;
    int warp = tid >> 5, lane = tid & 31;
    if (lane == 0) { rs[warp] = s; rss[warp] = ss; }
    __syncthreads();
    if (tid == 0) {
        float ts = 0.f, tss = 0.f;
        #pragma unroll
        for (int i = 0; i < 8; i++) { ts += rs[i]; tss += rss[i]; }
        float mean = ts * (1.0f/EMB);
        float var  = tss * (1.0f/EMB) - mean*mean;
        s_mean = mean;
        s_rstd = rsqrtf(var + 1e-5f);
    }
    __syncthreads();
    float mean = s_mean, rstd = s_rstd;
    float4 sc = ((const float4*)scale)[tid];
    float4 sh = ((const float4*)shift)[tid];
    float4 o;
    o.x = sc.x*(v.x-mean)*rstd + sh.x;
    o.y = sc.y*(v.y-mean)*rstd + sh.y;
    o.z = sc.z*(v.z-mean)*rstd + sh.z;
    o.w = sc.w*(v.w-mean)*rstd + sh.w;
    ((float4*)(y + (size_t)row*EMB))[tid] = o;
}

// ---------------- GELU (tanh form, exact reference math) --------------------
__device__ __forceinline__ float gelu_f(float x)
{
    float x3 = x*x*x;
    float t  = tanhf(0.7978845608028654f*(x + 0.044715f*x3));
    return 0.5f*x*(1.0f + t);
}

// ---------------- SGEMM: C = A@B (+bias) (+GELU) (+residual) ----------------
// 128x128 block tile, BK=16, 256 threads, 8x8 per-thread tile.
template<int ACT>   // 0 = none, 1 = gelu
__global__ __launch_bounds__(256)
void sgemm(const float* __restrict__ A, const float* __restrict__ B,
           const float* __restrict__ bias, const float* __restrict__ res,
           float* __restrict__ C, int M, int N, int K)
{
    __shared__ float As[16][128];
    __shared__ float Bs[16][128];

    int bn = blockIdx.x * 128;
    int bm = blockIdx.y * 128;
    int tid = threadIdx.x;
    int tx = tid & 15, ty = tid >> 4;

    float acc[8][8];
    #pragma unroll
    for (int i = 0; i < 8; i++)
        #pragma unroll
        for (int j = 0; j < 8; j++) acc[i][j] = 0.f;

    const float* Ap = A + (size_t)bm * K;
    const float* Bp = B + bn;

    int ar0 = tid >> 2;            // 0..63
    int ac0 = (tid & 3) * 4;       // 0,4,8,12
    int br0 = tid >> 5;            // 0..7
    int bc0 = (tid & 31) * 4;      // 0..124

    for (int k0 = 0; k0 < K; k0 += 16) {
        #pragma unroll
        for (int i = 0; i < 2; i++) {
            int r = ar0 + i * 64;
            float4 a = *(const float4*)(Ap + (size_t)r * K + k0 + ac0);
            As[ac0+0][r] = a.x;
            As[ac0+1][r] = a.y;
            As[ac0+2][r] = a.z;
            As[ac0+3][r] = a.w;
            int rb = br0 + i * 8;
            float4 b = *(const float4*)(Bp + (size_t)(k0 + rb) * N + bc0);
            *(float4*)&Bs[rb][bc0] = b;
        }
        __syncthreads();
        #pragma unroll
        for (int kk = 0; kk < 16; kk++) {
            float a[8], b[8];
            #pragma unroll
            for (int i = 0; i < 8; i++) a[i] = As[kk][ty*8 + i];
            #pragma unroll
            for (int j = 0; j < 8; j++) b[j] = Bs[kk][tx*8 + j];
            #pragma unroll
            for (int i = 0; i < 8; i++)
                #pragma unroll
                for (int j = 0; j < 8; j++)
                    acc[i][j] += a[i] * b[j];
        }
        __syncthreads();
    }

    #pragma unroll
    for (int i = 0; i < 8; i++) {
        int row = bm + ty*8 + i;
        #pragma unroll
        for (int j = 0; j < 8; j += 4) {
            int col = bn + tx*8 + j;
            float4 v;
            v.x = acc[i][j+0]; v.y = acc[i][j+1];
            v.z = acc[i][j+2]; v.w = acc[i][j+3];
            if (bias) {
                float4 bv = *(const float4*)(bias + col);
                v.x += bv.x; v.y += bv.y; v.z += bv.z; v.w += bv.w;
            }
            if (ACT == 1) {
                v.x = gelu_f(v.x); v.y = gelu_f(v.y);
                v.z = gelu_f(v.z); v.w = gelu_f(v.w);
            }
            if (res) {
                float4 rv = *(const float4*)(res + (size_t)row * N + col);
                v.x += rv.x; v.y += rv.y; v.z += rv.z; v.w += rv.w;
            }
            *(float4*)(C + (size_t)row * N + col) = v;
        }
    }
}

// ---------------- Flash attention (causal, fp32) ----------------------------
// grid: (SEQ/64, HEADS, BATCH); block: 64 threads; thread = one query row.
__global__ __launch_bounds__(64)
void attn_kernel(const float* __restrict__ Q, const float* __restrict__ K,
                 const float* __restrict__ V, float* __restrict__ O)
{
    __shared__ float Ks[64][64];
    __shared__ float Vs[64][64];
    __shared__ float Ss[64][64];   // Ss[j][tid] -> conflict-free

    int qt = blockIdx.x, h = blockIdx.y, b = blockIdx.z;
    int tid = threadIdx.x;
    int qrow = qt*64 + tid;
    size_t base = ((size_t)b * SEQ) * EMB + h * HD;

    float q[64];
    {
        const float4* qp = (const float4*)(Q + base + (size_t)qrow * EMB);
        #pragma unroll
        for (int d4 = 0; d4 < 16; d4++) {
            float4 v = qp[d4];
            q[d4*4+0] = v.x; q[d4*4+1] = v.y; q[d4*4+2] = v.z; q[d4*4+3] = v.w;
        }
    }
    float o[64];
    #pragma unroll
    for (int d = 0; d < 64; d++) o[d] = 0.f;
    float m = -INFINITY, l = 0.f;

    for (int kb = 0; kb <= qt; kb++) {
        #pragma unroll
        for (int it = 0; it < 16; it++) {
            int f = tid + it * 64;          // float4 index 0..1023
            int r = f >> 4;                 // row 0..63
            int c = (f & 15) * 4;           // col 0..60
            size_t goff = base + (size_t)(kb*64 + r) * EMB + c;
            *(float4*)&Ks[r][c] = *(const float4*)(K + goff);
            *(float4*)&Vs[r][c] = *(const float4*)(V + goff);
        }
        __syncthreads();

        bool diag = (kb == qt);
        float tmax = -INFINITY;
        for (int j = 0; j < 64; j++) {
            float d0 = 0.f, d1 = 0.f, d2 = 0.f, d3 = 0.f;
            #pragma unroll
            for (int d = 0; d < 64; d += 4) {
                d0 += q[d+0] * Ks[j][d+0];
                d1 += q[d+1] * Ks[j][d+1];
                d2 += q[d+2] * Ks[j][d+2];
                d3 += q[d+3] * Ks[j][d+3];
            }
            float s = ((d0 + d1) + (d2 + d3)) * 0.125f;   // 1/sqrt(64)
            if (diag && (kb*64 + j) > qrow) s = -INFINITY;
            Ss[j][tid] = s;
            tmax = fmaxf(tmax, s);
        }
        float newm = fmaxf(m, tmax);
        float corr = __expf(m - newm);       // first tile: exp(-inf)=0
        l *= corr;
        #pragma unroll
        for (int d = 0; d < 64; d++) o[d] *= corr;
        for (int j = 0; j < 64; j++) {
            float p = __expf(Ss[j][tid] - newm);   // masked -> 0
            l += p;
            #pragma unroll
            for (int d = 0; d < 64; d++) o[d] += p * Vs[j][d];
        }
        m = newm;
        __syncthreads();
    }

    float inv = 1.0f / l;
    float4* op = (float4*)(O + base + (size_t)qrow * EMB);
    #pragma unroll
    for (int d4 = 0; d4 < 16; d4++) {
        float4 v;
        v.x = o[d4*4+0]*inv; v.y = o[d4*4+1]*inv;
        v.z = o[d4*4+2]*inv; v.w = o[d4*4+3]*inv;
        op[d4] = v;
    }
}

// ---------------- launch -----------------------------------------------------
extern "C" void kernel_launch(void* const* d_in, const int* in_sizes, int n_in,
                              void* d_out, int out_size)
{
    const float* x      = (const float*)d_in[0];
    const float* ln1_s  = (const float*)d_in[1];
    const float* ln1_b  = (const float*)d_in[2];
    const float* Wq     = (const float*)d_in[3];
    const float* Wk     = (const float*)d_in[4];
    const float* Wv     = (const float*)d_in[5];
    const float* Wo     = (const float*)d_in[6];
    const float* bo     = (const float*)d_in[7];
    const float* ln2_s  = (const float*)d_in[8];
    const float* ln2_b  = (const float*)d_in[9];
    const float* W1     = (const float*)d_in[10];
    const float* b1     = (const float*)d_in[11];
    const float* W2     = (const float*)d_in[12];
    const float* b2     = (const float*)d_in[13];
    float* out = (float*)d_out;

    void* parena = nullptr;
    cudaGetSymbolAddress(&parena, g_arena);
    float* arena = (float*)parena;
    float* h   = arena + SLOT*0;
    float* q   = arena + SLOT*1;
    float* k   = arena + SLOT*2;
    float* v   = arena + SLOT*3;
    float* ctx = arena + SLOT*4;
    float* x1  = arena + SLOT*5;
    float* h2  = arena + SLOT*6;
    float* ffn = arena + SLOT*7;

    dim3 gE(EMB/128, MTOK/128);     // N=1024 GEMMs
    dim3 gF(FF/128,  MTOK/128);     // N=4096 GEMM

    // 1) LN1
    ln_kernel<<<MTOK, 256>>>(x, ln1_s, ln1_b, h);
    // 2) Q,K,V projections
    sgemm<0><<<gE, 256>>>(h, Wq, nullptr, nullptr, q, MTOK, EMB, EMB);
    sgemm<0><<<gE, 256>>>(h, Wk, nullptr, nullptr, k, MTOK, EMB, EMB);
    sgemm<0><<<gE, 256>>>(h, Wv, nullptr, nullptr, v, MTOK, EMB, EMB);
    // 3) causal flash attention
    attn_kernel<<<dim3(SEQ/64, HEADS, BATCH), 64>>>(q, k, v, ctx);
    // 4) output projection + residual:  x1 = x + ctx@Wo + bo
    sgemm<0><<<gE, 256>>>(ctx, Wo, bo, x, x1, MTOK, EMB, EMB);
    // 5) LN2
    ln_kernel<<<MTOK, 256>>>(x1, ln2_s, ln2_b, h2);
    // 6) FFN up + GELU
    sgemm<1><<<gF, 256>>>(h2, W1, b1, nullptr, ffn, MTOK, FF, EMB);
    // 7) FFN down + bias + residual -> out
    sgemm<0><<<gE, 256>>>(ffn, W2, b2, x1, out, MTOK, EMB, FF);
}

// round 4
// speedup vs baseline: 1.5244x; 1.5244x over previous
#include <cuda_runtime.h>
#include <cuda_bf16.h>
#include <math.h>
#include <stdint.h>

#define EMB   1024
#define SEQ   2048
#define BATCH 2
#define MTOK  (BATCH*SEQ)   // 4096 rows
#define FF    4096
#define HEADS 16
#define HD    64

// ---------------- single scratch arena (static; no cudaMalloc) -------------
// float region:
//   h,q,k,v,ctx,x1,h2 : 7 slots of MTOK*EMB
//   ffn               : MTOK*FF
// uint32 region (bf16x2 pair planes of transposed weights):
//   4 EMB weights: 8 planes x 524288
//   W1: 2 planes x 2097152 ; W2: 2 planes x 2097152
#define SLOT ((size_t)MTOK*EMB)
#define OF_FFN (SLOT*7)
#define OF_WT  (OF_FFN + (size_t)MTOK*FF)
#define PLANE_E  524288ull            // 1024*1024/2
#define PLANE_F  2097152ull           // 1024*4096/2
__device__ float g_arena[OF_WT + 8ull*PLANE_E + 4ull*PLANE_F];

// ---------------- helpers ---------------------------------------------------
__device__ __forceinline__ void split2(float x0, float x1, uint32_t& hi, uint32_t& lo)
{
    __nv_bfloat16 h0 = __float2bfloat16(x0);
    __nv_bfloat16 h1 = __float2bfloat16(x1);
    __nv_bfloat16 l0 = __float2bfloat16(x0 - __bfloat162float(h0));
    __nv_bfloat16 l1 = __float2bfloat16(x1 - __bfloat162float(h1));
    hi = (uint32_t)__bfloat16_as_ushort(h0) | ((uint32_t)__bfloat16_as_ushort(h1) << 16);
    lo = (uint32_t)__bfloat16_as_ushort(l0) | ((uint32_t)__bfloat16_as_ushort(l1) << 16);
}

__device__ __forceinline__ void mma16816(float* c, const uint32_t* a, const uint32_t* b)
{
    asm volatile(
        "mma.sync.aligned.m16n8k16.row.col.f32.bf16.bf16.f32 "
        "{%0,%1,%2,%3},{%4,%5,%6,%7},{%8,%9},{%0,%1,%2,%3};"
        : "+f"(c[0]), "+f"(c[1]), "+f"(c[2]), "+f"(c[3])
        : "r"(a[0]), "r"(a[1]), "r"(a[2]), "r"(a[3]), "r"(b[0]), "r"(b[1]));
}

__device__ __forceinline__ float gelu_f(float x)
{
    float x3 = x*x*x;
    float t  = tanhf(0.7978845608028654f*(x + 0.044715f*x3));
    return 0.5f*x*(1.0f + t);
}

// ---------------- weight prepass: W[K][N] -> Wt_hi/lo[n][kpair] -------------
__global__ __launch_bounds__(256)
void split_transpose(const float* __restrict__ W, uint32_t* __restrict__ Oh,
                     uint32_t* __restrict__ Ol, int K, int N)
{
    __shared__ float t[32][33];
    int n0 = blockIdx.x*32, k0 = blockIdx.y*32;
    int tid = threadIdx.x;
    #pragma unroll
    for (int i = 0; i < 4; i++) {
        int idx = tid + 256*i;
        int r = idx >> 5, c = idx & 31;
        t[r][c] = W[(size_t)(k0 + r)*N + n0 + c];
    }
    __syncthreads();
    #pragma unroll
    for (int i = 0; i < 2; i++) {
        int s = tid + 256*i;
        int n = s >> 4, p = s & 15;
        uint32_t h, l;
        split2(t[2*p][n], t[2*p+1][n], h, l);
        size_t off = (size_t)(n0 + n)*(K >> 1) + (k0 >> 1) + p;
        Oh[off] = h; Ol[off] = l;
    }
}

// ---------------- bf16x3 tensor-core GEMM ----------------------------------
// C[M,N] = A[M,K] (fp32, split on the fly) @ Bt (pre-split pair planes)
// 128x128 tile, 8 warps (2m x 4n), warp tile 64x32, BK=32 (2 k16 steps).
template<int ACT>   // 0 = none, 1 = gelu
__global__ __launch_bounds__(256)
void hgemm3(const float* __restrict__ A,
            const uint32_t* __restrict__ Bth, const uint32_t* __restrict__ Btl,
            const float* __restrict__ bias, const float* __restrict__ res,
            float* __restrict__ C, int M, int N, int K)
{
    __shared__ uint32_t Ah[128][20], Al[128][20], Bh[128][20], Bl[128][20];

    const int tid  = threadIdx.x;
    const int bn   = blockIdx.x * 128;
    const int bm   = blockIdx.y * 128;
    const int warp = tid >> 5, lane = tid & 31;
    const int wm   = (warp >> 2) * 64;     // 0 or 64
    const int wn   = (warp & 3) * 32;      // 0,32,64,96
    const int gr   = lane >> 2;            // 0..7
    const int cc   = lane & 3;             // 0..3

    float acc[4][4][4];
    #pragma unroll
    for (int i = 0; i < 4; i++)
        #pragma unroll
        for (int j = 0; j < 4; j++)
            #pragma unroll
            for (int r = 0; r < 4; r++) acc[i][j][r] = 0.f;

    const int Kp = K >> 1;   // pairs per row of Bt

    // prefetch iter 0
    float4 aP[4];
    uint4  bPh[2], bPl[2];
    #pragma unroll
    for (int i = 0; i < 4; i++) {
        int f = tid + 256*i; int r = f >> 3; int kc = (f & 7)*4;
        aP[i] = *(const float4*)(A + (size_t)(bm + r)*K + kc);
    }
    #pragma unroll
    for (int i = 0; i < 2; i++) {
        int g = tid + 256*i; int r = g >> 2; int q = (g & 3)*4;
        size_t off = (size_t)(bn + r)*Kp + q;
        bPh[i] = *(const uint4*)(Bth + off);
        bPl[i] = *(const uint4*)(Btl + off);
    }

    for (int k0 = 0; k0 < K; k0 += 32) {
        // store prefetched tile to smem (split A on the fly)
        #pragma unroll
        for (int i = 0; i < 4; i++) {
            int f = tid + 256*i; int r = f >> 3; int p = (f & 7)*2;
            uint32_t h0, l0, h1, l1;
            split2(aP[i].x, aP[i].y, h0, l0);
            split2(aP[i].z, aP[i].w, h1, l1);
            uint2 hv; hv.x = h0; hv.y = h1;
            uint2 lv; lv.x = l0; lv.y = l1;
            *(uint2*)&Ah[r][p] = hv;
            *(uint2*)&Al[r][p] = lv;
        }
        #pragma unroll
        for (int i = 0; i < 2; i++) {
            int g = tid + 256*i; int r = g >> 2; int q = (g & 3)*4;
            *(uint4*)&Bh[r][q] = bPh[i];
            *(uint4*)&Bl[r][q] = bPl[i];
        }
        __syncthreads();

        // prefetch next tile
        if (k0 + 32 < K) {
            #pragma unroll
            for (int i = 0; i < 4; i++) {
                int f = tid + 256*i; int r = f >> 3; int kc = (f & 7)*4;
                aP[i] = *(const float4*)(A + (size_t)(bm + r)*K + k0 + 32 + kc);
            }
            #pragma unroll
            for (int i = 0; i < 2; i++) {
                int g = tid + 256*i; int r = g >> 2; int q = (g & 3)*4;
                size_t off = (size_t)(bn + r)*Kp + ((k0 + 32) >> 1) + q;
                bPh[i] = *(const uint4*)(Bth + off);
                bPl[i] = *(const uint4*)(Btl + off);
            }
        }

        // 2 x k16 steps
        #pragma unroll
        for (int s = 0; s < 2; s++) {
            const int kp = s*8;
            uint32_t ah[4][4], al[4][4];
            #pragma unroll
            for (int mi = 0; mi < 4; mi++) {
                int base = wm + mi*16;
                ah[mi][0] = Ah[base + gr    ][kp + cc    ];
                ah[mi][1] = Ah[base + gr + 8][kp + cc    ];
                ah[mi][2] = Ah[base + gr    ][kp + cc + 4];
                ah[mi][3] = Ah[base + gr + 8][kp + cc + 4];
                al[mi][0] = Al[base + gr    ][kp + cc    ];
                al[mi][1] = Al[base + gr + 8][kp + cc    ];
                al[mi][2] = Al[base + gr    ][kp + cc + 4];
                al[mi][3] = Al[base + gr + 8][kp + cc + 4];
            }
            uint32_t bh[4][2], bl[4][2];
            #pragma unroll
            for (int nj = 0; nj < 4; nj++) {
                int col = wn + nj*8;
                bh[nj][0] = Bh[col + gr][kp + cc    ];
                bh[nj][1] = Bh[col + gr][kp + cc + 4];
                bl[nj][0] = Bl[col + gr][kp + cc    ];
                bl[nj][1] = Bl[col + gr][kp + cc + 4];
            }
            #pragma unroll
            for (int mi = 0; mi < 4; mi++)
                #pragma unroll
                for (int nj = 0; nj < 4; nj++) {
                    mma16816(acc[mi][nj], ah[mi], bh[nj]);
                    mma16816(acc[mi][nj], ah[mi], bl[nj]);
                    mma16816(acc[mi][nj], al[mi], bh[nj]);
                }
        }
        __syncthreads();
    }

    // epilogue
    #pragma unroll
    for (int mi = 0; mi < 4; mi++) {
        int r0 = bm + wm + mi*16 + gr;
        #pragma unroll
        for (int nj = 0; nj < 4; nj++) {
            int col = bn + wn + nj*8 + cc*2;
            float2 v0, v1;
            v0.x = acc[mi][nj][0]; v0.y = acc[mi][nj][1];
            v1.x = acc[mi][nj][2]; v1.y = acc[mi][nj][3];
            if (bias) {
                float2 bv = *(const float2*)(bias + col);
                v0.x += bv.x; v0.y += bv.y; v1.x += bv.x; v1.y += bv.y;
            }
            if (ACT == 1) {
                v0.x = gelu_f(v0.x); v0.y = gelu_f(v0.y);
                v1.x = gelu_f(v1.x); v1.y = gelu_f(v1.y);
            }
            if (res) {
                float2 r0v = *(const float2*)(res + (size_t)r0*N + col);
                float2 r1v = *(const float2*)(res + (size_t)(r0+8)*N + col);
                v0.x += r0v.x; v0.y += r0v.y; v1.x += r1v.x; v1.y += r1v.y;
            }
            *(float2*)(C + (size_t)r0*N + col)     = v0;
            *(float2*)(C + (size_t)(r0+8)*N + col) = v1;
        }
    }
}

// ---------------- LayerNorm: one block per row ------------------------------
__global__ __launch_bounds__(256)
void ln_kernel(const float* __restrict__ x, const float* __restrict__ scale,
               const float* __restrict__ shift, float* __restrict__ y)
{
    int row = blockIdx.x;
    int tid = threadIdx.x;
    const float4* xr = (const float4*)(x + (size_t)row*EMB);
    float4 v = xr[tid];
    float s  = v.x+v.y+v.z+v.w;
    float ss = v.x*v.x+v.y*v.y+v.z*v.z+v.w*v.w;
    #pragma unroll
    for (int o = 16; o > 0; o >>= 1) {
        s  += __shfl_xor_sync(0xffffffffu, s,  o);
        ss += __shfl_xor_sync(0xffffffffu, ss, o);
    }
    __shared__ float rs[8], rss[8];
    __shared__ float s_mean, s_rstd;
    int warp = tid >> 5, lane = tid & 31;
    if (lane == 0) { rs[warp] = s; rss[warp] = ss; }
    __syncthreads();
    if (tid == 0) {
        float ts = 0.f, tss = 0.f;
        #pragma unroll
        for (int i = 0; i < 8; i++) { ts += rs[i]; tss += rss[i]; }
        float mean = ts * (1.0f/EMB);
        float var  = tss * (1.0f/EMB) - mean*mean;
        s_mean = mean;
        s_rstd = rsqrtf(var + 1e-5f);
    }
    __syncthreads();
    float mean = s_mean, rstd = s_rstd;
    float4 sc = ((const float4*)scale)[tid];
    float4 sh = ((const float4*)shift)[tid];
    float4 o;
    o.x = sc.x*(v.x-mean)*rstd + sh.x;
    o.y = sc.y*(v.y-mean)*rstd + sh.y;
    o.z = sc.z*(v.z-mean)*rstd + sh.z;
    o.w = sc.w*(v.w-mean)*rstd + sh.w;
    ((float4*)(y + (size_t)row*EMB))[tid] = o;
}

// ---------------- Flash attention (causal, fp32) ----------------------------
__global__ __launch_bounds__(64)
void attn_kernel(const float* __restrict__ Q, const float* __restrict__ K,
                 const float* __restrict__ V, float* __restrict__ O)
{
    __shared__ float Ks[64][64];
    __shared__ float Vs[64][64];
    __shared__ float Ss[64][64];

    int qt = blockIdx.x, h = blockIdx.y, b = blockIdx.z;
    int tid = threadIdx.x;
    int qrow = qt*64 + tid;
    size_t base = ((size_t)b * SEQ) * EMB + h * HD;

    float q[64];
    {
        const float4* qp = (const float4*)(Q + base + (size_t)qrow * EMB);
        #pragma unroll
        for (int d4 = 0; d4 < 16; d4++) {
            float4 v = qp[d4];
            q[d4*4+0] = v.x; q[d4*4+1] = v.y; q[d4*4+2] = v.z; q[d4*4+3] = v.w;
        }
    }
    float o[64];
    #pragma unroll
    for (int d = 0; d < 64; d++) o[d] = 0.f;
    float m = -INFINITY, l = 0.f;

    for (int kb = 0; kb <= qt; kb++) {
        #pragma unroll
        for (int it = 0; it < 16; it++) {
            int f = tid + it * 64;
            int r = f >> 4;
            int c = (f & 15) * 4;
            size_t goff = base + (size_t)(kb*64 + r) * EMB + c;
            *(float4*)&Ks[r][c] = *(const float4*)(K + goff);
            *(float4*)&Vs[r][c] = *(const float4*)(V + goff);
        }
        __syncthreads();

        bool diag = (kb == qt);
        float tmax = -INFINITY;
        for (int j = 0; j < 64; j++) {
            float d0 = 0.f, d1 = 0.f, d2 = 0.f, d3 = 0.f;
            #pragma unroll
            for (int d = 0; d < 64; d += 4) {
                d0 += q[d+0] * Ks[j][d+0];
                d1 += q[d+1] * Ks[j][d+1];
                d2 += q[d+2] * Ks[j][d+2];
                d3 += q[d+3] * Ks[j][d+3];
            }
            float s = ((d0 + d1) + (d2 + d3)) * 0.125f;
            if (diag && (kb*64 + j) > qrow) s = -INFINITY;
            Ss[j][tid] = s;
            tmax = fmaxf(tmax, s);
        }
        float newm = fmaxf(m, tmax);
        float corr = __expf(m - newm);
        l *= corr;
        #pragma unroll
        for (int d = 0; d < 64; d++) o[d] *= corr;
        for (int j = 0; j < 64; j++) {
            float p = __expf(Ss[j][tid] - newm);
            l += p;
            #pragma unroll
            for (int d = 0; d < 64; d++) o[d] += p * Vs[j][d];
        }
        m = newm;
        __syncthreads();
    }

    float inv = 1.0f / l;
    float4* op = (float4*)(O + base + (size_t)qrow * EMB);
    #pragma unroll
    for (int d4 = 0; d4 < 16; d4++) {
        float4 v;
        v.x = o[d4*4+0]*inv; v.y = o[d4*4+1]*inv;
        v.z = o[d4*4+2]*inv; v.w = o[d4*4+3]*inv;
        op[d4] = v;
    }
}

// ---------------- launch -----------------------------------------------------
extern "C" void kernel_launch(void* const* d_in, const int* in_sizes, int n_in,
                              void* d_out, int out_size)
{
    const float* x      = (const float*)d_in[0];
    const float* ln1_s  = (const float*)d_in[1];
    const float* ln1_b  = (const float*)d_in[2];
    const float* Wq     = (const float*)d_in[3];
    const float* Wk     = (const float*)d_in[4];
    const float* Wv     = (const float*)d_in[5];
    const float* Wo     = (const float*)d_in[6];
    const float* bo     = (const float*)d_in[7];
    const float* ln2_s  = (const float*)d_in[8];
    const float* ln2_b  = (const float*)d_in[9];
    const float* W1     = (const float*)d_in[10];
    const float* b1     = (const float*)d_in[11];
    const float* W2     = (const float*)d_in[12];
    const float* b2     = (const float*)d_in[13];
    float* out = (float*)d_out;

    void* parena = nullptr;
    cudaGetSymbolAddress(&parena, g_arena);
    float* arena = (float*)parena;
    float* h   = arena + SLOT*0;
    float* q   = arena + SLOT*1;
    float* k   = arena + SLOT*2;
    float* v   = arena + SLOT*3;
    float* ctx = arena + SLOT*4;
    float* x1  = arena + SLOT*5;
    float* h2  = arena + SLOT*6;
    float* ffn = arena + OF_FFN;

    uint32_t* wb  = (uint32_t*)(arena + OF_WT);
    uint32_t* wqh = wb;                 uint32_t* wql = wqh + PLANE_E;
    uint32_t* wkh = wql + PLANE_E;      uint32_t* wkl = wkh + PLANE_E;
    uint32_t* wvh = wkl + PLANE_E;      uint32_t* wvl = wvh + PLANE_E;
    uint32_t* woh = wvl + PLANE_E;      uint32_t* wol = woh + PLANE_E;
    uint32_t* w1h = wol + PLANE_E;      uint32_t* w1l = w1h + PLANE_F;
    uint32_t* w2h = w1l + PLANE_F;      uint32_t* w2l = w2h + PLANE_F;

    // 0) weight prepass (transpose + bf16 hi/lo split)
    dim3 pE(EMB/32, EMB/32);
    split_transpose<<<pE, 256>>>(Wq, wqh, wql, EMB, EMB);
    split_transpose<<<pE, 256>>>(Wk, wkh, wkl, EMB, EMB);
    split_transpose<<<pE, 256>>>(Wv, wvh, wvl, EMB, EMB);
    split_transpose<<<pE, 256>>>(Wo, woh, wol, EMB, EMB);
    split_transpose<<<dim3(FF/32,  EMB/32), 256>>>(W1, w1h, w1l, EMB, FF);
    split_transpose<<<dim3(EMB/32, FF/32 ), 256>>>(W2, w2h, w2l, FF, EMB);

    dim3 gE(EMB/128, MTOK/128);
    dim3 gF(FF/128,  MTOK/128);

    // 1) LN1
    ln_kernel<<<MTOK, 256>>>(x, ln1_s, ln1_b, h);
    // 2) Q,K,V projections
    hgemm3<0><<<gE, 256>>>(h, wqh, wql, nullptr, nullptr, q, MTOK, EMB, EMB);
    hgemm3<0><<<gE, 256>>>(h, wkh, wkl, nullptr, nullptr, k, MTOK, EMB, EMB);
    hgemm3<0><<<gE, 256>>>(h, wvh, wvl, nullptr, nullptr, v, MTOK, EMB, EMB);
    // 3) causal flash attention
    attn_kernel<<<dim3(SEQ/64, HEADS, BATCH), 64>>>(q, k, v, ctx);
    // 4) output projection + residual:  x1 = x + ctx@Wo + bo
    hgemm3<0><<<gE, 256>>>(ctx, woh, wol, bo, x, x1, MTOK, EMB, EMB);
    // 5) LN2
    ln_kernel<<<MTOK, 256>>>(x1, ln2_s, ln2_b, h2);
    // 6) FFN up + GELU
    hgemm3<1><<<gF, 256>>>(h2, w1h, w1l, b1, nullptr, ffn, MTOK, FF, EMB);
    // 7) FFN down + bias + residual -> out
    hgemm3<0><<<gE, 256>>>(ffn, w2h, w2l, b2, x1, out, MTOK, EMB, FF);
}

// round 6
// speedup vs baseline: 1.6443x; 1.0787x over previous
#include <cuda_runtime.h>
#include <cuda_bf16.h>
#include <math.h>
#include <stdint.h>

#define EMB   1024
#define SEQ   2048
#define BATCH 2
#define MTOK  (BATCH*SEQ)   // 4096
#define FF    4096
#define HEADS 16
#define HD    64
#define QKS   3072          // fused qkv row stride

// ---------------- arena ------------------------------------------------------
// qkv fp32 [MTOK][3072] : 3*SLOT
// x1  fp32              : SLOT
// h,h2,ctx hi/lo planes : 6*HSLOT
// ffn hi/lo planes      : 2*FSLOT
// weight planes (u32)   : wqkv 2*PLANE_Q + wo 2*PLANE_E + w1 2*PLANE_F + w2 2*PLANE_F
#define SLOT    ((size_t)MTOK*EMB)
#define HSLOT   (SLOT/2)
#define FSLOT   ((size_t)MTOK*FF/2)
#define PLANE_Q 1572864ull      // 3072*512
#define PLANE_E 524288ull       // 1024*512
#define PLANE_F 2097152ull      // 4096*512 (or 1024*2048)
#define OF_X1   (SLOT*3)
#define OF_HB   (SLOT*4)
#define OF_FFN  (OF_HB + HSLOT*6)
#define OF_WT   (OF_FFN + FSLOT*2)
__device__ float g_arena[OF_WT + 2ull*PLANE_Q + 2ull*PLANE_E + 4ull*PLANE_F];

// ---------------- helpers ----------------------------------------------------
__device__ __forceinline__ void split2(float x0, float x1, uint32_t& hi, uint32_t& lo)
{
    __nv_bfloat16 h0 = __float2bfloat16(x0);
    __nv_bfloat16 h1 = __float2bfloat16(x1);
    __nv_bfloat16 l0 = __float2bfloat16(x0 - __bfloat162float(h0));
    __nv_bfloat16 l1 = __float2bfloat16(x1 - __bfloat162float(h1));
    hi = (uint32_t)__bfloat16_as_ushort(h0) | ((uint32_t)__bfloat16_as_ushort(h1) << 16);
    lo = (uint32_t)__bfloat16_as_ushort(l0) | ((uint32_t)__bfloat16_as_ushort(l1) << 16);
}

__device__ __forceinline__ float gelu_f(float x)
{
    float x3 = x*x*x;
    float t  = tanhf(0.7978845608028654f*(x + 0.044715f*x3));
    return 0.5f*x*(1.0f + t);
}

__device__ __forceinline__ uint32_t smem_u32(const void* p)
{
    return (uint32_t)__cvta_generic_to_shared(p);
}

#define CP16(dst, src) \
    asm volatile("cp.async.cg.shared.global [%0], [%1], 16;\n" :: "r"(dst), "l"(src))
#define CP_COMMIT() asm volatile("cp.async.commit_group;\n" ::: "memory")
#define CP_WAIT0()  asm volatile("cp.async.wait_group 0;\n" ::: "memory")
#define CP_WAIT1()  asm volatile("cp.async.wait_group 1;\n" ::: "memory")

__device__ __forceinline__ void mma16816(float* c, const uint32_t* a, const uint32_t* b)
{
    asm volatile(
        "mma.sync.aligned.m16n8k16.row.col.f32.bf16.bf16.f32 "
        "{%0,%1,%2,%3},{%4,%5,%6,%7},{%8,%9},{%0,%1,%2,%3};"
        : "+f"(c[0]), "+f"(c[1]), "+f"(c[2]), "+f"(c[3])
        : "r"(a[0]), "r"(a[1]), "r"(a[2]), "r"(a[3]), "r"(b[0]), "r"(b[1]));
}

__device__ __forceinline__ void ldsm4(uint32_t& r0, uint32_t& r1, uint32_t& r2,
                                      uint32_t& r3, uint32_t addr)
{
    asm volatile("ldmatrix.sync.aligned.m8n8.x4.shared.b16 {%0,%1,%2,%3}, [%4];"
        : "=r"(r0), "=r"(r1), "=r"(r2), "=r"(r3) : "r"(addr));
}

// ---------------- weight prepass: W[K][N] -> Wt hi/lo [n][k] bf16 -----------
__global__ __launch_bounds__(256)
void split_transpose(const float* __restrict__ W, uint32_t* __restrict__ Oh,
                     uint32_t* __restrict__ Ol, int K, int N)
{
    __shared__ float t[32][33];
    int n0 = blockIdx.x*32, k0 = blockIdx.y*32;
    int tid = threadIdx.x;
    #pragma unroll
    for (int i = 0; i < 4; i++) {
        int idx = tid + 256*i;
        int r = idx >> 5, c = idx & 31;
        t[r][c] = W[(size_t)(k0 + r)*N + n0 + c];
    }
    __syncthreads();
    #pragma unroll
    for (int i = 0; i < 2; i++) {
        int s = tid + 256*i;
        int n = s >> 4, p = s & 15;
        uint32_t h, l;
        split2(t[2*p][n], t[2*p+1][n], h, l);
        size_t off = (size_t)(n0 + n)*(K >> 1) + (k0 >> 1) + p;
        Oh[off] = h; Ol[off] = l;
    }
}

// ---------------- HMMA bf16x3 GEMM with ldmatrix + cp.async -----------------
// C[M,N] = A @ Bt^T,  A planes [M][K] bf16, Bt planes [N][K] bf16.
// BM=BN=128, BK=32, 2 stages, 8 warps (2m x 4n), warp tile 64x32.
// SMEM/stage: AH 0 | AL 10240 | BH 20480 | BL 30720  (row stride 80B), stage stride 40960.
#define RS 80
#define STG 40960
#define GEMM_SMEM (2*STG)

template<int ACT, int OUTP>   // ACT: gelu ; OUTP: 0 fp32, 1 bf16 planes
__global__ __launch_bounds__(256)
void hgemm(const __nv_bfloat16* __restrict__ Ah_, const __nv_bfloat16* __restrict__ Al_,
           const __nv_bfloat16* __restrict__ Bh_, const __nv_bfloat16* __restrict__ Bl_,
           const float* __restrict__ bias, const float* __restrict__ res,
           float* __restrict__ Cf, uint32_t* __restrict__ Ch, uint32_t* __restrict__ Cl,
           int M, int N, int K)
{
    extern __shared__ char smem[];
    const uint32_t sb = smem_u32(smem);
    const int tid  = threadIdx.x;
    const int wid  = tid >> 5;
    const int lane = tid & 31;
    const int bn   = blockIdx.x * 128;
    const int bm   = blockIdx.y * 128;
    const int wm   = (wid >> 2) * 64;
    const int wn   = (wid & 3) * 32;
    const int gr   = lane >> 2;
    const int cc   = lane & 3;
    const int nc   = K / 32;

    float acc[4][4][4];
    #pragma unroll
    for (int i = 0; i < 4; i++)
        #pragma unroll
        for (int j = 0; j < 4; j++)
            #pragma unroll
            for (int r = 0; r < 4; r++) acc[i][j][r] = 0.f;

    // cp.async loader: chunk ck -> stage s
    const int lr = tid >> 2;          // row 0..63 (x2 iterations -> 128)
    const int lj = (tid & 3);         // 16B chunk 0..3
    auto load_chunk = [&](int ck, int s) {
        const uint32_t stb = sb + s*STG;
        const int k0 = ck * 32;
        #pragma unroll
        for (int i = 0; i < 2; i++) {
            int r = lr + i*64;
            uint32_t d = stb + r*RS + lj*16;
            CP16(d,         Ah_ + (size_t)(bm + r)*K + k0 + lj*8);
            CP16(d + 10240, Al_ + (size_t)(bm + r)*K + k0 + lj*8);
            CP16(d + 20480, Bh_ + (size_t)(bn + r)*K + k0 + lj*8);
            CP16(d + 30720, Bl_ + (size_t)(bn + r)*K + k0 + lj*8);
        }
        CP_COMMIT();
    };

    // ldmatrix per-lane base offsets
    const uint32_t aoff = (uint32_t)((wm + (lane & 15))*RS + ((lane >> 4) & 1)*16);
    const uint32_t boff = (uint32_t)((wn + (lane & 15))*RS + ((lane >> 4) & 1)*16);

    load_chunk(0, 0);
    if (nc > 1) load_chunk(1, 1);

    for (int i = 0; i < nc; i++) {
        const int s = i & 1;
        if (i + 1 < nc) CP_WAIT1(); else CP_WAIT0();
        __syncthreads();

        const uint32_t stb = sb + s*STG;
        #pragma unroll
        for (int t = 0; t < 2; t++) {
            const uint32_t ka = t*32;
            uint32_t ah[4][4], al[4][4];
            #pragma unroll
            for (int mi = 0; mi < 4; mi++) {
                ldsm4(ah[mi][0], ah[mi][1], ah[mi][2], ah[mi][3],
                      stb + aoff + mi*16*RS + ka);
                ldsm4(al[mi][0], al[mi][1], al[mi][2], al[mi][3],
                      stb + 10240 + aoff + mi*16*RS + ka);
            }
            uint32_t bh[4][2], bl[4][2];
            #pragma unroll
            for (int p = 0; p < 2; p++) {
                uint32_t r0, r1, r2, r3;
                ldsm4(r0, r1, r2, r3, stb + 20480 + boff + p*16*RS + ka);
                bh[2*p][0] = r0; bh[2*p][1] = r2;
                bh[2*p+1][0] = r1; bh[2*p+1][1] = r3;
                ldsm4(r0, r1, r2, r3, stb + 30720 + boff + p*16*RS + ka);
                bl[2*p][0] = r0; bl[2*p][1] = r2;
                bl[2*p+1][0] = r1; bl[2*p+1][1] = r3;
            }
            #pragma unroll
            for (int mi = 0; mi < 4; mi++)
                #pragma unroll
                for (int nj = 0; nj < 4; nj++) {
                    mma16816(acc[mi][nj], ah[mi], bh[nj]);
                    mma16816(acc[mi][nj], ah[mi], bl[nj]);
                    mma16816(acc[mi][nj], al[mi], bh[nj]);
                }
        }
        __syncthreads();
        if (i + 2 < nc) load_chunk(i + 2, s);
    }

    // epilogue
    #pragma unroll
    for (int mi = 0; mi < 4; mi++) {
        int r0 = bm + wm + mi*16 + gr;
        #pragma unroll
        for (int nj = 0; nj < 4; nj++) {
            int col = bn + wn + nj*8 + cc*2;
            float2 v0, v1;
            v0.x = acc[mi][nj][0]; v0.y = acc[mi][nj][1];
            v1.x = acc[mi][nj][2]; v1.y = acc[mi][nj][3];
            if (bias) {
                float2 bv = *(const float2*)(bias + col);
                v0.x += bv.x; v0.y += bv.y; v1.x += bv.x; v1.y += bv.y;
            }
            if (ACT == 1) {
                v0.x = gelu_f(v0.x); v0.y = gelu_f(v0.y);
                v1.x = gelu_f(v1.x); v1.y = gelu_f(v1.y);
            }
            if (res) {
                float2 ra = *(const float2*)(res + (size_t)r0*N + col);
                float2 rb = *(const float2*)(res + (size_t)(r0+8)*N + col);
                v0.x += ra.x; v0.y += ra.y; v1.x += rb.x; v1.y += rb.y;
            }
            if (OUTP == 0) {
                *(float2*)(Cf + (size_t)r0*N + col)     = v0;
                *(float2*)(Cf + (size_t)(r0+8)*N + col) = v1;
            } else {
                uint32_t h, l;
                split2(v0.x, v0.y, h, l);
                size_t p0 = ((size_t)r0*N + col) >> 1;
                Ch[p0] = h; Cl[p0] = l;
                split2(v1.x, v1.y, h, l);
                size_t p1 = ((size_t)(r0+8)*N + col) >> 1;
                Ch[p1] = h; Cl[p1] = l;
            }
        }
    }
}

// ---------------- LayerNorm -> bf16 hi/lo planes ----------------------------
__global__ __launch_bounds__(256)
void ln_planes(const float* __restrict__ x, const float* __restrict__ scale,
               const float* __restrict__ shift,
               uint32_t* __restrict__ yh, uint32_t* __restrict__ yl)
{
    int row = blockIdx.x;
    int tid = threadIdx.x;
    const float4* xr = (const float4*)(x + (size_t)row*EMB);
    float4 v = xr[tid];
    float s  = v.x+v.y+v.z+v.w;
    float ss = v.x*v.x+v.y*v.y+v.z*v.z+v.w*v.w;
    #pragma unroll
    for (int o = 16; o > 0; o >>= 1) {
        s  += __shfl_xor_sync(0xffffffffu, s,  o);
        ss += __shfl_xor_sync(0xffffffffu, ss, o);
    }
    __shared__ float rs[8], rss[8];
    __shared__ float s_mean, s_rstd;
    int warp = tid >> 5, lane = tid & 31;
    if (lane == 0) { rs[warp] = s; rss[warp] = ss; }
    __syncthreads();
    if (tid == 0) {
        float ts = 0.f, tss = 0.f;
        #pragma unroll
        for (int i = 0; i < 8; i++) { ts += rs[i]; tss += rss[i]; }
        float mean = ts * (1.0f/EMB);
        float var  = tss * (1.0f/EMB) - mean*mean;
        s_mean = mean;
        s_rstd = rsqrtf(var + 1e-5f);
    }
    __syncthreads();
    float mean = s_mean, rstd = s_rstd;
    float4 sc = ((const float4*)scale)[tid];
    float4 sh = ((const float4*)shift)[tid];
    float o0 = sc.x*(v.x-mean)*rstd + sh.x;
    float o1 = sc.y*(v.y-mean)*rstd + sh.y;
    float o2 = sc.z*(v.z-mean)*rstd + sh.z;
    float o3 = sc.w*(v.w-mean)*rstd + sh.w;
    uint32_t h0, l0, h1, l1;
    split2(o0, o1, h0, l0);
    split2(o2, o3, h1, l1);
    size_t p = (size_t)row*(EMB/2) + tid*2;
    uint2 hv; hv.x = h0; hv.y = h1;
    uint2 lv; lv.x = l0; lv.y = l1;
    *(uint2*)(yh + p) = hv;
    *(uint2*)(yl + p) = lv;
}

// ---------------- Flash attention (fused qkv in, planes out) ----------------
__global__ __launch_bounds__(64)
void attn_kernel(const float* __restrict__ QKV,
                 uint32_t* __restrict__ Oh, uint32_t* __restrict__ Ol)
{
    __shared__ float Ks[64][64];
    __shared__ float Vs[64][64];
    __shared__ float Ss[64][64];

    int qt = blockIdx.x, h = blockIdx.y, b = blockIdx.z;
    int tid = threadIdx.x;
    int qrow = qt*64 + tid;
    size_t base = ((size_t)b * SEQ) * QKS + h * HD;

    float q[64];
    {
        const float4* qp = (const float4*)(QKV + base + (size_t)qrow * QKS);
        #pragma unroll
        for (int d4 = 0; d4 < 16; d4++) {
            float4 v = qp[d4];
            q[d4*4+0] = v.x; q[d4*4+1] = v.y; q[d4*4+2] = v.z; q[d4*4+3] = v.w;
        }
    }
    float o[64];
    #pragma unroll
    for (int d = 0; d < 64; d++) o[d] = 0.f;
    float m = -INFINITY, l = 0.f;

    for (int kb = 0; kb <= qt; kb++) {
        #pragma unroll
        for (int it = 0; it < 16; it++) {
            int f = tid + it * 64;
            int r = f >> 4;
            int c = (f & 15) * 4;
            size_t goff = base + (size_t)(kb*64 + r) * QKS + c;
            *(float4*)&Ks[r][c] = *(const float4*)(QKV + goff + 1024);
            *(float4*)&Vs[r][c] = *(const float4*)(QKV + goff + 2048);
        }
        __syncthreads();

        bool diag = (kb == qt);
        float tmax = -INFINITY;
        for (int j = 0; j < 64; j++) {
            float d0 = 0.f, d1 = 0.f, d2 = 0.f, d3 = 0.f;
            #pragma unroll
            for (int d = 0; d < 64; d += 4) {
                d0 += q[d+0] * Ks[j][d+0];
                d1 += q[d+1] * Ks[j][d+1];
                d2 += q[d+2] * Ks[j][d+2];
                d3 += q[d+3] * Ks[j][d+3];
            }
            float s = ((d0 + d1) + (d2 + d3)) * 0.125f;
            if (diag && (kb*64 + j) > qrow) s = -INFINITY;
            Ss[j][tid] = s;
            tmax = fmaxf(tmax, s);
        }
        float newm = fmaxf(m, tmax);
        float corr = __expf(m - newm);
        l *= corr;
        #pragma unroll
        for (int d = 0; d < 64; d++) o[d] *= corr;
        for (int j = 0; j < 64; j++) {
            float p = __expf(Ss[j][tid] - newm);
            l += p;
            #pragma unroll
            for (int d = 0; d < 64; d++) o[d] += p * Vs[j][d];
        }
        m = newm;
        __syncthreads();
    }

    float inv = 1.0f / l;
    size_t p0 = ((size_t)(b*SEQ + qrow) * EMB + h * HD) >> 1;
    #pragma unroll
    for (int i = 0; i < 16; i++) {
        uint32_t h0, l0, h1, l1;
        split2(o[4*i+0]*inv, o[4*i+1]*inv, h0, l0);
        split2(o[4*i+2]*inv, o[4*i+3]*inv, h1, l1);
        uint2 hv; hv.x = h0; hv.y = h1;
        uint2 lv; lv.x = l0; lv.y = l1;
        *(uint2*)(Oh + p0 + 2*i) = hv;
        *(uint2*)(Ol + p0 + 2*i) = lv;
    }
}

// ---------------- launch -----------------------------------------------------
extern "C" void kernel_launch(void* const* d_in, const int* in_sizes, int n_in,
                              void* d_out, int out_size)
{
    const float* x      = (const float*)d_in[0];
    const float* ln1_s  = (const float*)d_in[1];
    const float* ln1_b  = (const float*)d_in[2];
    const float* Wq     = (const float*)d_in[3];
    const float* Wk     = (const float*)d_in[4];
    const float* Wv     = (const float*)d_in[5];
    const float* Wo     = (const float*)d_in[6];
    const float* bo     = (const float*)d_in[7];
    const float* ln2_s  = (const float*)d_in[8];
    const float* ln2_b  = (const float*)d_in[9];
    const float* W1     = (const float*)d_in[10];
    const float* b1     = (const float*)d_in[11];
    const float* W2     = (const float*)d_in[12];
    const float* b2     = (const float*)d_in[13];
    float* out = (float*)d_out;

    void* parena = nullptr;
    cudaGetSymbolAddress(&parena, g_arena);
    float* arena = (float*)parena;

    float* qkv = arena;
    float* x1  = arena + OF_X1;
    uint32_t* h_hi   = (uint32_t*)(arena + OF_HB + HSLOT*0);
    uint32_t* h_lo   = (uint32_t*)(arena + OF_HB + HSLOT*1);
    uint32_t* h2_hi  = (uint32_t*)(arena + OF_HB + HSLOT*2);
    uint32_t* h2_lo  = (uint32_t*)(arena + OF_HB + HSLOT*3);
    uint32_t* ctx_hi = (uint32_t*)(arena + OF_HB + HSLOT*4);
    uint32_t* ctx_lo = (uint32_t*)(arena + OF_HB + HSLOT*5);
    uint32_t* ffn_hi = (uint32_t*)(arena + OF_FFN);
    uint32_t* ffn_lo = (uint32_t*)(arena + OF_FFN + FSLOT);

    uint32_t* wb   = (uint32_t*)(arena + OF_WT);
    uint32_t* wqvh = wb;                  uint32_t* wqvl = wqvh + PLANE_Q;
    uint32_t* woh  = wqvl + PLANE_Q;      uint32_t* wol  = woh  + PLANE_E;
    uint32_t* w1h  = wol  + PLANE_E;      uint32_t* w1l  = w1h  + PLANE_F;
    uint32_t* w2h  = w1l  + PLANE_F;      uint32_t* w2l  = w2h  + PLANE_F;

    cudaFuncSetAttribute(hgemm<0,0>, cudaFuncAttributeMaxDynamicSharedMemorySize, GEMM_SMEM);
    cudaFuncSetAttribute(hgemm<1,1>, cudaFuncAttributeMaxDynamicSharedMemorySize, GEMM_SMEM);

    // 0) weight prepass; qkv weights interleave into one [3072][512] plane pair
    dim3 pE(EMB/32, EMB/32);
    split_transpose<<<pE, 256>>>(Wq, wqvh,            wqvl,            EMB, EMB);
    split_transpose<<<pE, 256>>>(Wk, wqvh + 1024*512, wqvl + 1024*512, EMB, EMB);
    split_transpose<<<pE, 256>>>(Wv, wqvh + 2048*512, wqvl + 2048*512, EMB, EMB);
    split_transpose<<<pE, 256>>>(Wo, woh, wol, EMB, EMB);
    split_transpose<<<dim3(FF/32,  EMB/32), 256>>>(W1, w1h, w1l, EMB, FF);
    split_transpose<<<dim3(EMB/32, FF/32 ), 256>>>(W2, w2h, w2l, FF, EMB);

    dim3 gQ(QKS/128, MTOK/128);     // (24, 32)
    dim3 gE(EMB/128, MTOK/128);     // (8, 32)
    dim3 gF(FF/128,  MTOK/128);     // (32, 32)

    // 1) LN1 -> h planes
    ln_planes<<<MTOK, 256>>>(x, ln1_s, ln1_b, h_hi, h_lo);
    // 2) fused QKV projection (fp32 out, N=3072)
    hgemm<0,0><<<gQ, 256, GEMM_SMEM>>>((__nv_bfloat16*)h_hi, (__nv_bfloat16*)h_lo,
        (__nv_bfloat16*)wqvh, (__nv_bfloat16*)wqvl, nullptr, nullptr, qkv, nullptr, nullptr,
        MTOK, QKS, EMB);
    // 3) causal flash attention -> ctx planes
    attn_kernel<<<dim3(SEQ/64, HEADS, BATCH), 64>>>(qkv, ctx_hi, ctx_lo);
    // 4) x1 = x + ctx@Wo + bo
    hgemm<0,0><<<gE, 256, GEMM_SMEM>>>((__nv_bfloat16*)ctx_hi, (__nv_bfloat16*)ctx_lo,
        (__nv_bfloat16*)woh, (__nv_bfloat16*)wol, bo, x, x1, nullptr, nullptr,
        MTOK, EMB, EMB);
    // 5) LN2 -> h2 planes
    ln_planes<<<MTOK, 256>>>(x1, ln2_s, ln2_b, h2_hi, h2_lo);
    // 6) FFN up + GELU -> ffn planes
    hgemm<1,1><<<gF, 256, GEMM_SMEM>>>((__nv_bfloat16*)h2_hi, (__nv_bfloat16*)h2_lo,
        (__nv_bfloat16*)w1h, (__nv_bfloat16*)w1l, b1, nullptr, nullptr, ffn_hi, ffn_lo,
        MTOK, FF, EMB);
    // 7) out = x1 + ffn@W2 + b2
    hgemm<0,0><<<gE, 256, GEMM_SMEM>>>((__nv_bfloat16*)ffn_hi, (__nv_bfloat16*)ffn_lo,
        (__nv_bfloat16*)w2h, (__nv_bfloat16*)w2l, b2, x1, out, nullptr, nullptr,
        MTOK, EMB, FF);
}

// round 9
// speedup vs baseline: 2.5202x; 1.5326x over previous
#include <cuda_runtime.h>
#include <cuda_bf16.h>
#include <math.h>
#include <stdint.h>

#define EMB   1024
#define SEQ   2048
#define BATCH 2
#define MTOK  (BATCH*SEQ)   // 4096
#define FF    4096
#define HEADS 16
#define HD    64
#define QKS   3072          // fused qkv col count

// ---------------- arena ------------------------------------------------------
#define SLOT    ((size_t)MTOK*EMB)
#define HSLOT   (SLOT/2)
#define FSLOT   ((size_t)MTOK*FF/2)
#define PLANE_Q 1572864ull
#define PLANE_E 524288ull
#define PLANE_F 2097152ull
#define OF_X1   (SLOT*3)
#define OF_HB   (SLOT*4)
#define OF_FFN  (OF_HB + HSLOT*6)
#define OF_WT   (OF_FFN + FSLOT*2)
__device__ float g_arena[OF_WT + 2ull*PLANE_Q + 2ull*PLANE_E + 4ull*PLANE_F];

// ---------------- helpers ----------------------------------------------------
__device__ __forceinline__ void split2(float x0, float x1, uint32_t& hi, uint32_t& lo)
{
    __nv_bfloat16 h0 = __float2bfloat16(x0);
    __nv_bfloat16 h1 = __float2bfloat16(x1);
    __nv_bfloat16 l0 = __float2bfloat16(x0 - __bfloat162float(h0));
    __nv_bfloat16 l1 = __float2bfloat16(x1 - __bfloat162float(h1));
    hi = (uint32_t)__bfloat16_as_ushort(h0) | ((uint32_t)__bfloat16_as_ushort(h1) << 16);
    lo = (uint32_t)__bfloat16_as_ushort(l0) | ((uint32_t)__bfloat16_as_ushort(l1) << 16);
}

__device__ __forceinline__ float gelu_f(float x)
{
    float x3 = x*x*x;
    float t  = tanhf(0.7978845608028654f*(x + 0.044715f*x3));
    return 0.5f*x*(1.0f + t);
}

__device__ __forceinline__ uint32_t smem_u32(const void* p)
{
    return (uint32_t)__cvta_generic_to_shared(p);
}

#define CP16(dst, src) \
    asm volatile("cp.async.cg.shared.global [%0], [%1], 16;\n" :: "r"(dst), "l"(src))
#define CP_COMMIT() asm volatile("cp.async.commit_group;\n" ::: "memory")
#define CP_WAIT0()  asm volatile("cp.async.wait_group 0;\n" ::: "memory")
#define CP_WAIT1()  asm volatile("cp.async.wait_group 1;\n" ::: "memory")

__device__ __forceinline__ void mma16816(float* c, const uint32_t* a, const uint32_t* b)
{
    asm volatile(
        "mma.sync.aligned.m16n8k16.row.col.f32.bf16.bf16.f32 "
        "{%0,%1,%2,%3},{%4,%5,%6,%7},{%8,%9},{%0,%1,%2,%3};"
        : "+f"(c[0]), "+f"(c[1]), "+f"(c[2]), "+f"(c[3])
        : "r"(a[0]), "r"(a[1]), "r"(a[2]), "r"(a[3]), "r"(b[0]), "r"(b[1]));
}

__device__ __forceinline__ void ldsm4(uint32_t& r0, uint32_t& r1, uint32_t& r2,
                                      uint32_t& r3, uint32_t addr)
{
    asm volatile("ldmatrix.sync.aligned.m8n8.x4.shared.b16 {%0,%1,%2,%3}, [%4];"
        : "=r"(r0), "=r"(r1), "=r"(r2), "=r"(r3) : "r"(addr));
}

__device__ __forceinline__ void ldsm4t(uint32_t& r0, uint32_t& r1, uint32_t& r2,
                                       uint32_t& r3, uint32_t addr)
{
    asm volatile("ldmatrix.sync.aligned.m8n8.x4.trans.shared.b16 {%0,%1,%2,%3}, [%4];"
        : "=r"(r0), "=r"(r1), "=r"(r2), "=r"(r3) : "r"(addr));
}

// ---------------- weight prepass: W[K][N] -> Wt hi/lo [n][k] bf16 -----------
__global__ __launch_bounds__(256)
void split_transpose(const float* __restrict__ W, uint32_t* __restrict__ Oh,
                     uint32_t* __restrict__ Ol, int K, int N)
{
    __shared__ float t[32][33];
    int n0 = blockIdx.x*32, k0 = blockIdx.y*32;
    int tid = threadIdx.x;
    #pragma unroll
    for (int i = 0; i < 4; i++) {
        int idx = tid + 256*i;
        int r = idx >> 5, c = idx & 31;
        t[r][c] = W[(size_t)(k0 + r)*N + n0 + c];
    }
    __syncthreads();
    #pragma unroll
    for (int i = 0; i < 2; i++) {
        int s = tid + 256*i;
        int n = s >> 4, p = s & 15;
        uint32_t h, l;
        split2(t[2*p][n], t[2*p+1][n], h, l);
        size_t off = (size_t)(n0 + n)*(K >> 1) + (k0 >> 1) + p;
        Oh[off] = h; Ol[off] = l;
    }
}

// ---------------- HMMA bf16x3 GEMM ------------------------------------------
#define RS 80
#define STG 40960
#define GEMM_SMEM (2*STG)

template<int ACT, int OUTP>
__global__ __launch_bounds__(256)
void hgemm(const __nv_bfloat16* __restrict__ Ah_, const __nv_bfloat16* __restrict__ Al_,
           const __nv_bfloat16* __restrict__ Bh_, const __nv_bfloat16* __restrict__ Bl_,
           const float* __restrict__ bias, const float* __restrict__ res,
           float* __restrict__ Cf, uint32_t* __restrict__ Ch, uint32_t* __restrict__ Cl,
           int M, int N, int K)
{
    extern __shared__ char smem[];
    const uint32_t sb = smem_u32(smem);
    const int tid  = threadIdx.x;
    const int wid  = tid >> 5;
    const int lane = tid & 31;
    const int bn   = blockIdx.x * 128;
    const int bm   = blockIdx.y * 128;
    const int wm   = (wid >> 2) * 64;
    const int wn   = (wid & 3) * 32;
    const int gr   = lane >> 2;
    const int cc   = lane & 3;
    const int nc   = K / 32;

    float acc[4][4][4];
    #pragma unroll
    for (int i = 0; i < 4; i++)
        #pragma unroll
        for (int j = 0; j < 4; j++)
            #pragma unroll
            for (int r = 0; r < 4; r++) acc[i][j][r] = 0.f;

    const int lr = tid >> 2;
    const int lj = (tid & 3);
    auto load_chunk = [&](int ck, int s) {
        const uint32_t stb = sb + s*STG;
        const int k0 = ck * 32;
        #pragma unroll
        for (int i = 0; i < 2; i++) {
            int r = lr + i*64;
            uint32_t d = stb + r*RS + lj*16;
            CP16(d,         Ah_ + (size_t)(bm + r)*K + k0 + lj*8);
            CP16(d + 10240, Al_ + (size_t)(bm + r)*K + k0 + lj*8);
            CP16(d + 20480, Bh_ + (size_t)(bn + r)*K + k0 + lj*8);
            CP16(d + 30720, Bl_ + (size_t)(bn + r)*K + k0 + lj*8);
        }
        CP_COMMIT();
    };

    const uint32_t aoff = (uint32_t)((wm + (lane & 15))*RS + ((lane >> 4) & 1)*16);
    const uint32_t boff = (uint32_t)((wn + (lane & 15))*RS + ((lane >> 4) & 1)*16);

    load_chunk(0, 0);
    if (nc > 1) load_chunk(1, 1);

    for (int i = 0; i < nc; i++) {
        const int s = i & 1;
        if (i + 1 < nc) CP_WAIT1(); else CP_WAIT0();
        __syncthreads();

        const uint32_t stb = sb + s*STG;
        #pragma unroll
        for (int t = 0; t < 2; t++) {
            const uint32_t ka = t*32;
            uint32_t ah[4][4], al[4][4];
            #pragma unroll
            for (int mi = 0; mi < 4; mi++) {
                ldsm4(ah[mi][0], ah[mi][1], ah[mi][2], ah[mi][3],
                      stb + aoff + mi*16*RS + ka);
                ldsm4(al[mi][0], al[mi][1], al[mi][2], al[mi][3],
                      stb + 10240 + aoff + mi*16*RS + ka);
            }
            uint32_t bh[4][2], bl[4][2];
            #pragma unroll
            for (int p = 0; p < 2; p++) {
                uint32_t r0, r1, r2, r3;
                ldsm4(r0, r1, r2, r3, stb + 20480 + boff + p*16*RS + ka);
                bh[2*p][0] = r0; bh[2*p][1] = r2;
                bh[2*p+1][0] = r1; bh[2*p+1][1] = r3;
                ldsm4(r0, r1, r2, r3, stb + 30720 + boff + p*16*RS + ka);
                bl[2*p][0] = r0; bl[2*p][1] = r2;
                bl[2*p+1][0] = r1; bl[2*p+1][1] = r3;
            }
            #pragma unroll
            for (int mi = 0; mi < 4; mi++)
                #pragma unroll
                for (int nj = 0; nj < 4; nj++) {
                    mma16816(acc[mi][nj], ah[mi], bh[nj]);
                    mma16816(acc[mi][nj], ah[mi], bl[nj]);
                    mma16816(acc[mi][nj], al[mi], bh[nj]);
                }
        }
        __syncthreads();
        if (i + 2 < nc) load_chunk(i + 2, s);
    }

    #pragma unroll
    for (int mi = 0; mi < 4; mi++) {
        int r0 = bm + wm + mi*16 + gr;
        #pragma unroll
        for (int nj = 0; nj < 4; nj++) {
            int col = bn + wn + nj*8 + cc*2;
            float2 v0, v1;
            v0.x = acc[mi][nj][0]; v0.y = acc[mi][nj][1];
            v1.x = acc[mi][nj][2]; v1.y = acc[mi][nj][3];
            if (bias) {
                float2 bv = *(const float2*)(bias + col);
                v0.x += bv.x; v0.y += bv.y; v1.x += bv.x; v1.y += bv.y;
            }
            if (ACT == 1) {
                v0.x = gelu_f(v0.x); v0.y = gelu_f(v0.y);
                v1.x = gelu_f(v1.x); v1.y = gelu_f(v1.y);
            }
            if (res) {
                float2 ra = *(const float2*)(res + (size_t)r0*N + col);
                float2 rb = *(const float2*)(res + (size_t)(r0+8)*N + col);
                v0.x += ra.x; v0.y += ra.y; v1.x += rb.x; v1.y += rb.y;
            }
            if (OUTP == 0) {
                *(float2*)(Cf + (size_t)r0*N + col)     = v0;
                *(float2*)(Cf + (size_t)(r0+8)*N + col) = v1;
            } else {
                uint32_t hh, ll;
                split2(v0.x, v0.y, hh, ll);
                size_t p0 = ((size_t)r0*N + col) >> 1;
                Ch[p0] = hh; Cl[p0] = ll;
                split2(v1.x, v1.y, hh, ll);
                size_t p1 = ((size_t)(r0+8)*N + col) >> 1;
                Ch[p1] = hh; Cl[p1] = ll;
            }
        }
    }
}

// ---------------- LayerNorm -> bf16 hi/lo planes ----------------------------
__global__ __launch_bounds__(256)
void ln_planes(const float* __restrict__ x, const float* __restrict__ scale,
               const float* __restrict__ shift,
               uint32_t* __restrict__ yh, uint32_t* __restrict__ yl)
{
    int row = blockIdx.x;
    int tid = threadIdx.x;
    const float4* xr = (const float4*)(x + (size_t)row*EMB);
    float4 v = xr[tid];
    float s  = v.x+v.y+v.z+v.w;
    float ss = v.x*v.x+v.y*v.y+v.z*v.z+v.w*v.w;
    #pragma unroll
    for (int o = 16; o > 0; o >>= 1) {
        s  += __shfl_xor_sync(0xffffffffu, s,  o);
        ss += __shfl_xor_sync(0xffffffffu, ss, o);
    }
    __shared__ float rs[8], rss[8];
    __shared__ float s_mean, s_rstd;
    int warp = tid >> 5, lane = tid & 31;
    if (lane == 0) { rs[warp] = s; rss[warp] = ss; }
    __syncthreads();
    if (tid == 0) {
        float ts = 0.f, tss = 0.f;
        #pragma unroll
        for (int i = 0; i < 8; i++) { ts += rs[i]; tss += rss[i]; }
        float mean = ts * (1.0f/EMB);
        float var  = tss * (1.0f/EMB) - mean*mean;
        s_mean = mean;
        s_rstd = rsqrtf(var + 1e-5f);
    }
    __syncthreads();
    float mean = s_mean, rstd = s_rstd;
    float4 sc = ((const float4*)scale)[tid];
    float4 sh = ((const float4*)shift)[tid];
    float o0 = sc.x*(v.x-mean)*rstd + sh.x;
    float o1 = sc.y*(v.y-mean)*rstd + sh.y;
    float o2 = sc.z*(v.z-mean)*rstd + sh.z;
    float o3 = sc.w*(v.w-mean)*rstd + sh.w;
    uint32_t h0, l0, h1, l1;
    split2(o0, o1, h0, l0);
    split2(o2, o3, h1, l1);
    size_t p = (size_t)row*(EMB/2) + tid*2;
    uint2 hv; hv.x = h0; hv.y = h1;
    uint2 lv; lv.x = l0; lv.y = l1;
    *(uint2*)(yh + p) = hv;
    *(uint2*)(yl + p) = lv;
}

// ---------------- Tensor-core flash attention -------------------------------
#define ARS   144
#define ATILE (64*ARS)      // 9216
#define ASTG  (4*ATILE)     // 36864
#define ATTN_SMEM (2*ASTG)  // 73728

__global__ __launch_bounds__(128)
void attn_mma(const __nv_bfloat16* __restrict__ Ph, const __nv_bfloat16* __restrict__ Pl,
              uint32_t* __restrict__ Oh, uint32_t* __restrict__ Ol)
{
    extern __shared__ char smem[];
    const uint32_t sb = smem_u32(smem);
    const int qt  = blockIdx.x;
    const int hd  = blockIdx.y;
    const int b   = blockIdx.z;
    const int tid = threadIdx.x;
    const int wid = tid >> 5, lane = tid & 31;
    const int gr  = lane >> 2, cc = lane & 3;
    const int nt  = qt + 1;
    const size_t tokbase = (size_t)b * SEQ;
    const int colq = hd * HD;

    // ---- stage Q (hi/lo) into smem, extract A-fragments ----
    #pragma unroll
    for (int i = 0; i < 4; i++) {
        int id = tid + 128*i; int r = id >> 3; int c = id & 7;
        size_t g = (tokbase + qt*64 + r)*QKS + colq + c*8;
        CP16(sb + r*ARS + c*16,         Ph + g);
        CP16(sb + ATILE + r*ARS + c*16, Pl + g);
    }
    CP_COMMIT(); CP_WAIT0();
    __syncthreads();

    uint32_t qfh[4][4], qfl[4][4];
    {
        const uint32_t qoff = (uint32_t)((wid*16 + (lane & 15))*ARS + ((lane >> 4) & 1)*16);
        #pragma unroll
        for (int t = 0; t < 4; t++) {
            ldsm4(qfh[t][0], qfh[t][1], qfh[t][2], qfh[t][3], sb + qoff + t*32);
            ldsm4(qfl[t][0], qfl[t][1], qfl[t][2], qfl[t][3], sb + ATILE + qoff + t*32);
        }
    }
    __syncthreads();

    float oacc[8][4];
    #pragma unroll
    for (int j = 0; j < 8; j++)
        #pragma unroll
        for (int r = 0; r < 4; r++) oacc[j][r] = 0.f;
    float m0 = -INFINITY, m1 = -INFINITY, l0 = 0.f, l1 = 0.f;

    auto load_kv = [&](int kb, int s) {
        const uint32_t base = sb + s*ASTG;
        #pragma unroll
        for (int i = 0; i < 4; i++) {
            int id = tid + 128*i; int r = id >> 3; int c = id & 7;
            size_t g = (tokbase + kb*64 + r)*QKS + colq + c*8;
            CP16(base           + r*ARS + c*16, Ph + g + 1024);   // K hi
            CP16(base + ATILE   + r*ARS + c*16, Pl + g + 1024);   // K lo
            CP16(base + 2*ATILE + r*ARS + c*16, Ph + g + 2048);   // V hi
            CP16(base + 3*ATILE + r*ARS + c*16, Pl + g + 2048);   // V lo
        }
        CP_COMMIT();
    };

    load_kv(0, 0);
    if (nt > 1) load_kv(1, 1);

    const uint32_t koff = (uint32_t)(((lane & 15))*ARS + ((lane >> 4) & 1)*16);
    const int rowg0 = qt*64 + wid*16 + gr;
    const int rowg1 = rowg0 + 8;

    for (int kb = 0; kb < nt; kb++) {
        const int s = kb & 1;
        if (kb + 1 < nt) CP_WAIT1(); else CP_WAIT0();
        __syncthreads();
        const uint32_t kbase = sb + s*ASTG;

        // ---- S = Q K^T (bf16x3) ----
        float sacc[8][4];
        #pragma unroll
        for (int j = 0; j < 8; j++)
            #pragma unroll
            for (int r = 0; r < 4; r++) sacc[j][r] = 0.f;

        #pragma unroll
        for (int t = 0; t < 4; t++) {
            uint32_t bh[8][2], bl[8][2];
            #pragma unroll
            for (int p = 0; p < 4; p++) {
                uint32_t a = kbase + p*16*ARS + koff + t*32;
                uint32_t r0, r1, r2, r3;
                ldsm4(r0, r1, r2, r3, a);
                bh[2*p][0] = r0; bh[2*p][1] = r2;
                bh[2*p+1][0] = r1; bh[2*p+1][1] = r3;
                ldsm4(r0, r1, r2, r3, a + ATILE);
                bl[2*p][0] = r0; bl[2*p][1] = r2;
                bl[2*p+1][0] = r1; bl[2*p+1][1] = r3;
            }
            #pragma unroll
            for (int j = 0; j < 8; j++) {
                mma16816(sacc[j], qfh[t], bh[j]);
                mma16816(sacc[j], qfh[t], bl[j]);
                mma16816(sacc[j], qfl[t], bh[j]);
            }
        }

        // ---- online softmax ----
        const bool diag = (kb == qt);
        float rmax0 = -INFINITY, rmax1 = -INFINITY;
        #pragma unroll
        for (int j = 0; j < 8; j++) {
            int c0 = kb*64 + j*8 + cc*2;
            float v0 = sacc[j][0]*0.125f, v1 = sacc[j][1]*0.125f;
            float v2 = sacc[j][2]*0.125f, v3 = sacc[j][3]*0.125f;
            if (diag) {
                if (c0     > rowg0) v0 = -INFINITY;
                if (c0 + 1 > rowg0) v1 = -INFINITY;
                if (c0     > rowg1) v2 = -INFINITY;
                if (c0 + 1 > rowg1) v3 = -INFINITY;
            }
            sacc[j][0] = v0; sacc[j][1] = v1; sacc[j][2] = v2; sacc[j][3] = v3;
            rmax0 = fmaxf(rmax0, fmaxf(v0, v1));
            rmax1 = fmaxf(rmax1, fmaxf(v2, v3));
        }
        rmax0 = fmaxf(rmax0, __shfl_xor_sync(0xffffffffu, rmax0, 1));
        rmax0 = fmaxf(rmax0, __shfl_xor_sync(0xffffffffu, rmax0, 2));
        rmax1 = fmaxf(rmax1, __shfl_xor_sync(0xffffffffu, rmax1, 1));
        rmax1 = fmaxf(rmax1, __shfl_xor_sync(0xffffffffu, rmax1, 2));
        float mn0 = fmaxf(m0, rmax0), mn1 = fmaxf(m1, rmax1);
        float cor0 = __expf(m0 - mn0), cor1 = __expf(m1 - mn1);
        m0 = mn0; m1 = mn1;
        float rs0 = 0.f, rs1 = 0.f;
        #pragma unroll
        for (int j = 0; j < 8; j++) {
            float p0 = __expf(sacc[j][0] - mn0);
            float p1 = __expf(sacc[j][1] - mn0);
            float p2 = __expf(sacc[j][2] - mn1);
            float p3 = __expf(sacc[j][3] - mn1);
            sacc[j][0] = p0; sacc[j][1] = p1; sacc[j][2] = p2; sacc[j][3] = p3;
            rs0 += p0 + p1; rs1 += p2 + p3;
        }
        rs0 += __shfl_xor_sync(0xffffffffu, rs0, 1);
        rs0 += __shfl_xor_sync(0xffffffffu, rs0, 2);
        rs1 += __shfl_xor_sync(0xffffffffu, rs1, 1);
        rs1 += __shfl_xor_sync(0xffffffffu, rs1, 2);
        l0 = l0*cor0 + rs0;
        l1 = l1*cor1 + rs1;
        #pragma unroll
        for (int j = 0; j < 8; j++) {
            oacc[j][0] *= cor0; oacc[j][1] *= cor0;
            oacc[j][2] *= cor1; oacc[j][3] *= cor1;
        }

        // ---- O += P V (bf16x3, V via ldmatrix.trans) ----
        #pragma unroll
        for (int t = 0; t < 4; t++) {
            uint32_t pah[4], pal[4];
            split2(sacc[2*t][0],   sacc[2*t][1],   pah[0], pal[0]);
            split2(sacc[2*t][2],   sacc[2*t][3],   pah[1], pal[1]);
            split2(sacc[2*t+1][0], sacc[2*t+1][1], pah[2], pal[2]);
            split2(sacc[2*t+1][2], sacc[2*t+1][3], pah[3], pal[3]);
            uint32_t vh[8][2], vl[8][2];
            #pragma unroll
            for (int u = 0; u < 4; u++) {
                uint32_t a = kbase + 2*ATILE + (16*t + (lane & 15))*ARS
                           + u*32 + ((lane >> 4) & 1)*16;
                uint32_t r0, r1, r2, r3;
                ldsm4t(r0, r1, r2, r3, a);
                vh[2*u][0] = r0; vh[2*u][1] = r1;
                vh[2*u+1][0] = r2; vh[2*u+1][1] = r3;
                ldsm4t(r0, r1, r2, r3, a + ATILE);
                vl[2*u][0] = r0; vl[2*u][1] = r1;
                vl[2*u+1][0] = r2; vl[2*u+1][1] = r3;
            }
            #pragma unroll
            for (int j = 0; j < 8; j++) {
                mma16816(oacc[j], pah, vh[j]);
                mma16816(oacc[j], pah, vl[j]);
                mma16816(oacc[j], pal, vh[j]);
            }
        }
        __syncthreads();
        if (kb + 2 < nt) load_kv(kb + 2, s);
    }

    // ---- finalize: /l, write ctx planes ----
    const float inv0 = 1.0f / l0, inv1 = 1.0f / l1;
    const size_t tok0 = tokbase + qt*64 + wid*16 + gr;
    #pragma unroll
    for (int j = 0; j < 8; j++) {
        int col = colq + j*8 + cc*2;
        uint32_t hh, ll;
        split2(oacc[j][0]*inv0, oacc[j][1]*inv0, hh, ll);
        size_t p0 = (tok0*EMB + col) >> 1;
        Oh[p0] = hh; Ol[p0] = ll;
        split2(oacc[j][2]*inv1, oacc[j][3]*inv1, hh, ll);
        size_t p1 = ((tok0 + 8)*EMB + col) >> 1;
        Oh[p1] = hh; Ol[p1] = ll;
    }
}

// ---------------- launch -----------------------------------------------------
extern "C" void kernel_launch(void* const* d_in, const int* in_sizes, int n_in,
                              void* d_out, int out_size)
{
    const float* x      = (const float*)d_in[0];
    const float* ln1_s  = (const float*)d_in[1];
    const float* ln1_b  = (const float*)d_in[2];
    const float* Wq     = (const float*)d_in[3];
    const float* Wk     = (const float*)d_in[4];
    const float* Wv     = (const float*)d_in[5];
    const float* Wo     = (const float*)d_in[6];
    const float* bo     = (const float*)d_in[7];
    const float* ln2_s  = (const float*)d_in[8];
    const float* ln2_b  = (const float*)d_in[9];
    const float* W1     = (const float*)d_in[10];
    const float* b1     = (const float*)d_in[11];
    const float* W2     = (const float*)d_in[12];
    const float* b2     = (const float*)d_in[13];
    float* out = (float*)d_out;

    void* parena = nullptr;
    cudaGetSymbolAddress(&parena, g_arena);
    float* arena = (float*)parena;

    uint32_t* qkvh = (uint32_t*)arena;
    uint32_t* qkvl = (uint32_t*)(arena + (size_t)MTOK*1536);
    float* x1  = arena + OF_X1;
    uint32_t* h_hi   = (uint32_t*)(arena + OF_HB + HSLOT*0);
    uint32_t* h_lo   = (uint32_t*)(arena + OF_HB + HSLOT*1);
    uint32_t* h2_hi  = (uint32_t*)(arena + OF_HB + HSLOT*2);
    uint32_t* h2_lo  = (uint32_t*)(arena + OF_HB + HSLOT*3);
    uint32_t* ctx_hi = (uint32_t*)(arena + OF_HB + HSLOT*4);
    uint32_t* ctx_lo = (uint32_t*)(arena + OF_HB + HSLOT*5);
    uint32_t* ffn_hi = (uint32_t*)(arena + OF_FFN);
    uint32_t* ffn_lo = (uint32_t*)(arena + OF_FFN + FSLOT);

    uint32_t* wb   = (uint32_t*)(arena + OF_WT);
    uint32_t* wqvh = wb;                  uint32_t* wqvl = wqvh + PLANE_Q;
    uint32_t* woh  = wqvl + PLANE_Q;      uint32_t* wol  = woh  + PLANE_E;
    uint32_t* w1h  = wol  + PLANE_E;      uint32_t* w1l  = w1h  + PLANE_F;
    uint32_t* w2h  = w1l  + PLANE_F;      uint32_t* w2l  = w2h  + PLANE_F;

    cudaFuncSetAttribute(hgemm<0,0>, cudaFuncAttributeMaxDynamicSharedMemorySize, GEMM_SMEM);
    cudaFuncSetAttribute(hgemm<0,1>, cudaFuncAttributeMaxDynamicSharedMemorySize, GEMM_SMEM);
    cudaFuncSetAttribute(hgemm<1,1>, cudaFuncAttributeMaxDynamicSharedMemorySize, GEMM_SMEM);
    cudaFuncSetAttribute(attn_mma,   cudaFuncAttributeMaxDynamicSharedMemorySize, ATTN_SMEM);

    // 0) weight prepass
    dim3 pE(EMB/32, EMB/32);
    split_transpose<<<pE, 256>>>(Wq, wqvh,            wqvl,            EMB, EMB);
    split_transpose<<<pE, 256>>>(Wk, wqvh + 1024*512, wqvl + 1024*512, EMB, EMB);
    split_transpose<<<pE, 256>>>(Wv, wqvh + 2048*512, wqvl + 2048*512, EMB, EMB);
    split_transpose<<<pE, 256>>>(Wo, woh, wol, EMB, EMB);
    split_transpose<<<dim3(FF/32,  EMB/32), 256>>>(W1, w1h, w1l, EMB, FF);
    split_transpose<<<dim3(EMB/32, FF/32 ), 256>>>(W2, w2h, w2l, FF, EMB);

    dim3 gQ(QKS/128, MTOK/128);
    dim3 gE(EMB/128, MTOK/128);
    dim3 gF(FF/128,  MTOK/128);

    // 1) LN1 -> h planes
    ln_planes<<<MTOK, 256>>>(x, ln1_s, ln1_b, h_hi, h_lo);
    // 2) fused QKV projection -> bf16 planes
    hgemm<0,1><<<gQ, 256, GEMM_SMEM>>>((__nv_bfloat16*)h_hi, (__nv_bfloat16*)h_lo,
        (__nv_bfloat16*)wqvh, (__nv_bfloat16*)wqvl, nullptr, nullptr, nullptr, qkvh, qkvl,
        MTOK, QKS, EMB);
    // 3) tensor-core causal flash attention -> ctx planes
    attn_mma<<<dim3(SEQ/64, HEADS, BATCH), 128, ATTN_SMEM>>>(
        (const __nv_bfloat16*)qkvh, (const __nv_bfloat16*)qkvl, ctx_hi, ctx_lo);
    // 4) x1 = x + ctx@Wo + bo
    hgemm<0,0><<<gE, 256, GEMM_SMEM>>>((__nv_bfloat16*)ctx_hi, (__nv_bfloat16*)ctx_lo,
        (__nv_bfloat16*)woh, (__nv_bfloat16*)wol, bo, x, x1, nullptr, nullptr,
        MTOK, EMB, EMB);
    // 5) LN2 -> h2 planes
    ln_planes<<<MTOK, 256>>>(x1, ln2_s, ln2_b, h2_hi, h2_lo);
    // 6) FFN up + GELU -> ffn planes
    hgemm<1,1><<<gF, 256, GEMM_SMEM>>>((__nv_bfloat16*)h2_hi, (__nv_bfloat16*)h2_lo,
        (__nv_bfloat16*)w1h, (__nv_bfloat16*)w1l, b1, nullptr, nullptr, ffn_hi, ffn_lo,
        MTOK, FF, EMB);
    // 7) out = x1 + ffn@W2 + b2
    hgemm<0,0><<<gE, 256, GEMM_SMEM>>>((__nv_bfloat16*)ffn_hi, (__nv_bfloat16*)ffn_lo,
        (__nv_bfloat16*)w2h, (__nv_bfloat16*)w2l, b2, x1, out, nullptr, nullptr,
        MTOK, EMB, FF);
}